// round 2
// baseline (speedup 1.0000x reference)
#include <cuda_runtime.h>
#include <math.h>

#define NN 16384      // total nodes (B*N)
#define NB 4096       // nodes per batch
#define KNB 16        // kNN K

// ---------------- scratch (no allocations allowed) ----------------
__device__ float g_xp[NN * 8];        // padded x: [x0..x5, |x|^2, 0]
__device__ int   g_nbr[NN * KNB];     // neighbor indices (global node ids)
__device__ float g_h[NN * 256];       // per-layer transformed features
__device__ float g_act0[NN * 256];    // activation ping
__device__ float g_act1[NN * 256];    // activation pong
__device__ float g_als[NN * 4];
__device__ float g_ald[NN * 4];

__device__ __forceinline__ float geluf(float v) {
    return 0.5f * v * (1.0f + erff(v * 0.7071067811865476f));
}

// ---------------- prep: pad + squared norms ----------------
__global__ void prep_kernel(const float* __restrict__ x, float* __restrict__ xp) {
    int i = blockIdx.x * blockDim.x + threadIdx.x;
    if (i >= NN) return;
    float s = 0.f;
    float v[6];
#pragma unroll
    for (int d = 0; d < 6; d++) { v[d] = x[i * 6 + d]; s += v[d] * v[d]; }
#pragma unroll
    for (int d = 0; d < 6; d++) xp[i * 8 + d] = v[d];
    xp[i * 8 + 6] = s;
    xp[i * 8 + 7] = 0.f;
}

// ---------------- kNN: one warp per query node ----------------
__global__ void knn_kernel(const float* __restrict__ xp, int* __restrict__ nbr) {
    const float SENT = 1e30f;
    int gwarp = (blockIdx.x * blockDim.x + threadIdx.x) >> 5;
    int lane = threadIdx.x & 31;
    if (gwarp >= NN) return;
    int q = gwarp;
    int base = (q >> 12) << 12;   // batch base

    const float4* xp4 = (const float4*)xp;
    float4 q0 = xp4[(size_t)q * 2];
    float4 q1 = xp4[(size_t)q * 2 + 1];
    float sqq = q1.z;

    float bd[KNB];
    int   bi[KNB];
#pragma unroll
    for (int s = 0; s < KNB; s++) { bd[s] = SENT; bi[s] = -1; }

    for (int j = lane; j < NB; j += 32) {
        int g = base + j;
        float4 c0 = xp4[(size_t)g * 2];
        float4 c1 = xp4[(size_t)g * 2 + 1];
        float dot = q0.x * c0.x + q0.y * c0.y + q0.z * c0.z + q0.w * c0.w
                  + q1.x * c1.x + q1.y * c1.y;
        float d2 = sqq + c1.z - 2.0f * dot;
        if (g == q) continue;
        if (d2 < bd[KNB - 1]) {
            bd[KNB - 1] = d2; bi[KNB - 1] = g;
#pragma unroll
            for (int s = KNB - 1; s > 0; s--) {
                if (bd[s] < bd[s - 1]) {
                    float td = bd[s]; bd[s] = bd[s - 1]; bd[s - 1] = td;
                    int   ti = bi[s]; bi[s] = bi[s - 1]; bi[s - 1] = ti;
                }
            }
        }
    }

    // stash sorted local lists in smem (dynamic indexing during merge)
    __shared__ float sd[8][32 * 17];
    __shared__ int   si[8][32 * 17];
    int w = threadIdx.x >> 5;
    int off = lane * 17;
#pragma unroll
    for (int s = 0; s < KNB; s++) { sd[w][off + s] = bd[s]; si[w][off + s] = bi[s]; }
    __syncwarp();

    int ptr = 0;
    for (int r = 0; r < KNB; r++) {
        float v = (ptr < KNB) ? sd[w][off + ptr] : SENT * 2.0f;
        float bv = v; int bl = lane;
#pragma unroll
        for (int o = 16; o > 0; o >>= 1) {
            float ov = __shfl_down_sync(0xffffffffu, bv, o);
            int   ol = __shfl_down_sync(0xffffffffu, bl, o);
            if (ov < bv) { bv = ov; bl = ol; }
        }
        bl = __shfl_sync(0xffffffffu, bl, 0);
        if (lane == bl) {
            nbr[q * KNB + r] = si[w][off + ptr];
            ptr++;
        }
    }
}

// ---------------- generic fp32 GEMM: C[M,N] = A[M,K] @ W[K,N] (+bias)(+gelu) ----------------
// blockDim.x == Nd; each block computes 16 rows x Nd cols.
__global__ void gemm_kernel(const float* __restrict__ A, const float* __restrict__ W,
                            const float* __restrict__ bias, float* __restrict__ C,
                            int Kd, int Nd, int actGelu) {
    __shared__ float Ws[32][256];
    __shared__ float As[16][33];
    int tx = threadIdx.x;
    int row0 = blockIdx.x * 16;
    float acc[16];
#pragma unroll
    for (int r = 0; r < 16; r++) acc[r] = 0.f;

    for (int k0 = 0; k0 < Kd; k0 += 32) {
        // W tile
        for (int k = 0; k < 32; k++) {
            int kk = k0 + k;
            Ws[k][tx] = (kk < Kd) ? W[(size_t)kk * Nd + tx] : 0.f;
        }
        // A tile
        for (int t = tx; t < 16 * 32; t += Nd) {
            int r = t >> 5, k = t & 31;
            int kk = k0 + k;
            As[r][k] = (kk < Kd) ? A[(size_t)(row0 + r) * Kd + kk] : 0.f;
        }
        __syncthreads();
#pragma unroll
        for (int k = 0; k < 32; k++) {
            float w = Ws[k][tx];
#pragma unroll
            for (int r = 0; r < 16; r++) acc[r] += As[r][k] * w;
        }
        __syncthreads();
    }
    float bb = bias ? bias[tx] : 0.f;
#pragma unroll
    for (int r = 0; r < 16; r++) {
        float v = acc[r] + bb;
        if (actGelu) v = geluf(v);
        C[(size_t)(row0 + r) * Nd + tx] = v;
    }
}

// ---------------- attention logits: one warp per node ----------------
__global__ void logits_kernel(const float* __restrict__ h, const float* __restrict__ a_s,
                              const float* __restrict__ a_d, float* __restrict__ als,
                              float* __restrict__ ald, int H, int C) {
    int gwarp = (blockIdx.x * blockDim.x + threadIdx.x) >> 5;
    int lane = threadIdx.x & 31;
    if (gwarp >= NN) return;
    const float* hr = h + (size_t)gwarp * H * C;
    for (int hh = 0; hh < H; hh++) {
        float ss = 0.f, sd = 0.f;
        for (int c = hh * C + lane; c < (hh + 1) * C; c += 32) {
            float v = hr[c];
            ss += v * a_s[c];
            sd += v * a_d[c];
        }
#pragma unroll
        for (int o = 16; o > 0; o >>= 1) {
            ss += __shfl_xor_sync(0xffffffffu, ss, o);
            sd += __shfl_xor_sync(0xffffffffu, sd, o);
        }
        if (lane == 0) { als[gwarp * H + hh] = ss; ald[gwarp * H + hh] = sd; }
    }
}

// ---------------- GAT aggregate: block per node, thread per feature ----------------
__global__ void aggregate_kernel(const float* __restrict__ h, const int* __restrict__ nbr,
                                 const float* __restrict__ als, const float* __restrict__ ald,
                                 const float* __restrict__ bias, float* __restrict__ out,
                                 int H, int C) {
    int F = H * C;
    int i = blockIdx.x;
    int t = threadIdx.x;
    __shared__ int   s_nbr[17];
    __shared__ float s_e[68];
    __shared__ float s_alpha[68];
    __shared__ float s_m[4], s_inv[4];

    if (t < 17) s_nbr[t] = (t < 16) ? nbr[i * KNB + t] : i;
    __syncthreads();

    int EH = 17 * H;
    if (t < EH) {
        int j = t / H, hh = t - j * H;
        float raw = als[(size_t)s_nbr[j] * H + hh] + ald[(size_t)i * H + hh];
        s_e[t] = raw > 0.f ? raw : 0.2f * raw;
    }
    __syncthreads();
    if (t < H) {
        float m = -1e30f;
        for (int j = 0; j < 17; j++) m = fmaxf(m, s_e[j * H + t]);
        float den = 0.f;
        for (int j = 0; j < 17; j++) den += expf(s_e[j * H + t] - m);
        s_m[t] = m; s_inv[t] = 1.0f / den;
    }
    __syncthreads();
    if (t < EH) {
        int hh = t % H;
        s_alpha[t] = expf(s_e[t] - s_m[hh]) * s_inv[hh];
    }
    __syncthreads();

    int hh = t / C;
    float acc = 0.f;
#pragma unroll 17
    for (int j = 0; j < 17; j++) {
        acc += s_alpha[j * H + hh] * h[(size_t)s_nbr[j] * F + t];
    }
    out[(size_t)i * F + t] = geluf(acc + bias[t]);
}

// ---------------- residual: y += x @ res_W + res_b ----------------
__global__ void residual_kernel(const float* __restrict__ x, const float* __restrict__ resW,
                                const float* __restrict__ resb, float* __restrict__ io) {
    int idx = blockIdx.x * blockDim.x + threadIdx.x;
    if (idx >= NN * 128) return;
    int i = idx >> 7, c = idx & 127;
    float acc = resb[c];
#pragma unroll
    for (int d = 0; d < 6; d++) acc += x[i * 6 + d] * resW[d * 128 + c];
    io[idx] += acc;
}

// ---------------- final: out[i, 0..5] = t2[i] @ m3_W + m3_b ----------------
__global__ void final_kernel(const float* __restrict__ A, const float* __restrict__ W,
                             const float* __restrict__ b, float* __restrict__ out) {
    __shared__ float Ws[64 * 6];
    __shared__ float sb[6];
    int t = threadIdx.x;
    for (int k = t; k < 64 * 6; k += blockDim.x) Ws[k] = W[k];
    if (t < 6) sb[t] = b[t];
    __syncthreads();

    int i = blockIdx.x * blockDim.x + t;
    if (i >= NN) return;
    float acc[6];
#pragma unroll
    for (int o = 0; o < 6; o++) acc[o] = sb[o];
    const float4* Ar = (const float4*)(A + (size_t)i * 64);
#pragma unroll
    for (int k4 = 0; k4 < 16; k4++) {
        float4 v = Ar[k4];
        int k = k4 * 4;
#pragma unroll
        for (int o = 0; o < 6; o++) {
            acc[o] += v.x * Ws[(k + 0) * 6 + o];
            acc[o] += v.y * Ws[(k + 1) * 6 + o];
            acc[o] += v.z * Ws[(k + 2) * 6 + o];
            acc[o] += v.w * Ws[(k + 3) * 6 + o];
        }
    }
#pragma unroll
    for (int o = 0; o < 6; o++) out[(size_t)i * 6 + o] = acc[o];
}

// ---------------- launch ----------------
extern "C" void kernel_launch(void* const* d_in, const int* in_sizes, int n_in,
                              void* d_out, int out_size) {
    const float* x    = (const float*)d_in[0];
    const float* W1   = (const float*)d_in[1];
    const float* as1  = (const float*)d_in[2];
    const float* ad1  = (const float*)d_in[3];
    const float* b1   = (const float*)d_in[4];
    const float* W2   = (const float*)d_in[5];
    const float* as2  = (const float*)d_in[6];
    const float* ad2  = (const float*)d_in[7];
    const float* b2   = (const float*)d_in[8];
    const float* W3   = (const float*)d_in[9];
    const float* as3  = (const float*)d_in[10];
    const float* ad3  = (const float*)d_in[11];
    const float* b3   = (const float*)d_in[12];
    const float* resW = (const float*)d_in[13];
    const float* resb = (const float*)d_in[14];
    const float* m1W  = (const float*)d_in[15];
    const float* m1b  = (const float*)d_in[16];
    const float* m2W  = (const float*)d_in[17];
    const float* m2b  = (const float*)d_in[18];
    const float* m3W  = (const float*)d_in[19];
    const float* m3b  = (const float*)d_in[20];

    float *xp, *h, *a0, *a1, *als, *ald;
    int* nbr;
    cudaGetSymbolAddress((void**)&xp,  g_xp);
    cudaGetSymbolAddress((void**)&nbr, g_nbr);
    cudaGetSymbolAddress((void**)&h,   g_h);
    cudaGetSymbolAddress((void**)&a0,  g_act0);
    cudaGetSymbolAddress((void**)&a1,  g_act1);
    cudaGetSymbolAddress((void**)&als, g_als);
    cudaGetSymbolAddress((void**)&ald, g_ald);

    prep_kernel<<<NN / 256, 256>>>(x, xp);
    knn_kernel<<<NN / 8, 256>>>(xp, nbr);

    // GAT layer 1 (6 -> 256, H=4, C=64)
    gemm_kernel<<<NN / 16, 256>>>(x, W1, nullptr, h, 6, 256, 0);
    logits_kernel<<<NN / 8, 256>>>(h, as1, ad1, als, ald, 4, 64);
    aggregate_kernel<<<NN, 256>>>(h, nbr, als, ald, b1, a0, 4, 64);

    // GAT layer 2 (256 -> 256, H=4, C=64)
    gemm_kernel<<<NN / 16, 256>>>(a0, W2, nullptr, h, 256, 256, 0);
    logits_kernel<<<NN / 8, 256>>>(h, as2, ad2, als, ald, 4, 64);
    aggregate_kernel<<<NN, 256>>>(h, nbr, als, ald, b2, a1, 4, 64);

    // GAT layer 3 (256 -> 128, H=1, C=128)
    gemm_kernel<<<NN / 16, 128>>>(a1, W3, nullptr, h, 256, 128, 0);
    logits_kernel<<<NN / 8, 256>>>(h, as3, ad3, als, ald, 1, 128);
    aggregate_kernel<<<NN, 128>>>(h, nbr, als, ald, b3, a0, 1, 128);

    // residual + MLP
    residual_kernel<<<(NN * 128) / 256, 256>>>(x, resW, resb, a0);
    gemm_kernel<<<NN / 16, 128>>>(a0, m1W, m1b, a1, 128, 128, 1);
    gemm_kernel<<<NN / 16, 64>>>(a1, m2W, m2b, h, 128, 64, 1);
    final_kernel<<<NN / 128, 128>>>(h, m3W, m3b, (float*)d_out);
}

// round 3
// speedup vs baseline: 1.8612x; 1.8612x over previous
#include <cuda_runtime.h>
#include <math.h>

#define NN 16384      // total nodes (B*N)
#define NB 4096       // nodes per batch
#define KNB 16        // kNN K

// ---------------- scratch (no allocations allowed) ----------------
__device__ float g_xp[NN * 8];        // padded x: [x0..x5, |x|^2, 0]
__device__ int   g_nbr[NN * KNB];     // neighbor indices (global node ids)
__device__ float g_h[NN * 256];       // per-layer transformed features
__device__ float g_act0[NN * 256];    // activation ping
__device__ float g_act1[NN * 256];    // activation pong
__device__ float g_als[NN * 4];
__device__ float g_ald[NN * 4];

__device__ __forceinline__ float geluf(float v) {
    return 0.5f * v * (1.0f + erff(v * 0.7071067811865476f));
}

// ---------------- prep: pad + squared norms ----------------
__global__ void prep_kernel(const float* __restrict__ x, float* __restrict__ xp) {
    int i = blockIdx.x * blockDim.x + threadIdx.x;
    if (i >= NN) return;
    float s = 0.f;
    float v[6];
#pragma unroll
    for (int d = 0; d < 6; d++) { v[d] = x[i * 6 + d]; s += v[d] * v[d]; }
#pragma unroll
    for (int d = 0; d < 6; d++) xp[i * 8 + d] = v[d];
    xp[i * 8 + 6] = s;
    xp[i * 8 + 7] = 0.f;
}

// ---------------- zero helper ----------------
__global__ void zero2_kernel(float* __restrict__ a, float* __restrict__ b, int n) {
    int i = blockIdx.x * blockDim.x + threadIdx.x;
    if (i < n) { a[i] = 0.f; b[i] = 0.f; }
}

// ---------------- kNN: warp per query; distributed global top-16 ----------------
// Lanes 0..31 hold a sorted (ascending) list of the best 32 distances seen;
// lanes 0..15 are the true top-16. Candidates are ballot-gated against the
// broadcast 16th-best; qualifying ones are shift-inserted via shuffles.
__global__ void knn_kernel(const float* __restrict__ xp, int* __restrict__ nbr) {
    int gwarp = (blockIdx.x * blockDim.x + threadIdx.x) >> 5;
    int lane = threadIdx.x & 31;
    if (gwarp >= NN) return;
    int q = gwarp;
    int base = q & ~(NB - 1);

    const float4* xp4 = (const float4*)xp;
    float4 q0 = xp4[(size_t)q * 2];
    float4 q1 = xp4[(size_t)q * 2 + 1];
    float sqq = q1.z;

    float s_d = 1e30f;
    int   s_i = -1;

    for (int j0 = 0; j0 < NB; j0 += 32) {
        int g = base + j0 + lane;
        float4 c0 = xp4[(size_t)g * 2];
        float4 c1 = xp4[(size_t)g * 2 + 1];
        float dot = q0.x * c0.x + q0.y * c0.y + q0.z * c0.z + q0.w * c0.w
                  + q1.x * c1.x + q1.y * c1.y;
        float d2 = sqq + c1.z - 2.0f * dot;
        if (g == q) d2 = 1e30f;

        float thresh = __shfl_sync(0xffffffffu, s_d, 15);
        unsigned ball = __ballot_sync(0xffffffffu, d2 < thresh);
        while (ball) {
            int src = __ffs(ball) - 1;
            ball &= ball - 1;
            float v  = __shfl_sync(0xffffffffu, d2, src);
            int   vi = base + j0 + src;
            float up_d = __shfl_up_sync(0xffffffffu, s_d, 1);
            int   up_i = __shfl_up_sync(0xffffffffu, s_i, 1);
            unsigned lt = __ballot_sync(0xffffffffu, s_d < v);
            int pos = __popc(lt);
            if (pos < 16) {
                if (lane == pos)      { s_d = v;    s_i = vi;   }
                else if (lane > pos)  { s_d = up_d; s_i = up_i; }
            }
        }
    }
    if (lane < 16) nbr[q * KNB + lane] = s_i;
}

// ---------------- register-tiled GEMM (+bias)(+gelu)(+fused attention logits) ----
// C[M,N] = A[M,K] @ W[K,N]. Block: 64 rows x 64 cols, 256 threads, 4x4/thread.
// If als != null: atomically accumulate als[i,h] += sum_c C[i,c]*a_s[c] (same for ald),
// where h = global_col >> headShift (64-col blocks never span a head).
__global__ void gemm_rt_kernel(const float* __restrict__ A, const float* __restrict__ W,
                               const float* __restrict__ bias, float* __restrict__ C,
                               int K, int N, int actGelu,
                               const float* __restrict__ a_s, const float* __restrict__ a_d,
                               float* __restrict__ als, float* __restrict__ ald,
                               int H, int headShift) {
    __shared__ float As[16][68];
    __shared__ float Ws[16][64];

    int t = threadIdx.x;
    int tc = t & 15;
    int tr = t >> 4;
    int row0 = blockIdx.x * 64;
    int c0 = blockIdx.y * 64;

    float acc[4][4];
#pragma unroll
    for (int r = 0; r < 4; r++)
#pragma unroll
        for (int c = 0; c < 4; c++) acc[r][c] = 0.f;

    for (int k0 = 0; k0 < K; k0 += 16) {
#pragma unroll
        for (int i = 0; i < 4; i++) {
            int idx = t + i * 256;
            int r = idx >> 4, k = idx & 15;
            int kk = k0 + k;
            As[k][r] = (kk < K) ? A[(size_t)(row0 + r) * K + kk] : 0.f;
        }
#pragma unroll
        for (int i = 0; i < 4; i++) {
            int idx = t + i * 256;
            int k = idx >> 6, c = idx & 63;
            int kk = k0 + k;
            Ws[k][c] = (kk < K) ? W[(size_t)kk * N + c0 + c] : 0.f;
        }
        __syncthreads();
#pragma unroll
        for (int k = 0; k < 16; k++) {
            float4 av = *(const float4*)&As[k][tr * 4];
            float4 wv = *(const float4*)&Ws[k][tc * 4];
            acc[0][0] += av.x * wv.x; acc[0][1] += av.x * wv.y; acc[0][2] += av.x * wv.z; acc[0][3] += av.x * wv.w;
            acc[1][0] += av.y * wv.x; acc[1][1] += av.y * wv.y; acc[1][2] += av.y * wv.z; acc[1][3] += av.y * wv.w;
            acc[2][0] += av.z * wv.x; acc[2][1] += av.z * wv.y; acc[2][2] += av.z * wv.z; acc[2][3] += av.z * wv.w;
            acc[3][0] += av.w * wv.x; acc[3][1] += av.w * wv.y; acc[3][2] += av.w * wv.z; acc[3][3] += av.w * wv.w;
        }
        __syncthreads();
    }

    // fused attention logits
    if (als) {
        float4 asv = *(const float4*)&a_s[c0 + tc * 4];
        float4 adv = *(const float4*)&a_d[c0 + tc * 4];
        float ps[4], pd[4];
#pragma unroll
        for (int r = 0; r < 4; r++) {
            ps[r] = acc[r][0] * asv.x + acc[r][1] * asv.y + acc[r][2] * asv.z + acc[r][3] * asv.w;
            pd[r] = acc[r][0] * adv.x + acc[r][1] * adv.y + acc[r][2] * adv.z + acc[r][3] * adv.w;
        }
#pragma unroll
        for (int off = 1; off <= 8; off <<= 1) {
#pragma unroll
            for (int r = 0; r < 4; r++) {
                ps[r] += __shfl_xor_sync(0xffffffffu, ps[r], off);
                pd[r] += __shfl_xor_sync(0xffffffffu, pd[r], off);
            }
        }
        if (tc == 0) {
            int hb = c0 >> headShift;
#pragma unroll
            for (int r = 0; r < 4; r++) {
                atomicAdd(&als[(size_t)(row0 + tr * 4 + r) * H + hb], ps[r]);
                atomicAdd(&ald[(size_t)(row0 + tr * 4 + r) * H + hb], pd[r]);
            }
        }
    }

    float4 bb = make_float4(0.f, 0.f, 0.f, 0.f);
    if (bias) bb = *(const float4*)&bias[c0 + tc * 4];
#pragma unroll
    for (int r = 0; r < 4; r++) {
        float v0 = acc[r][0] + bb.x, v1 = acc[r][1] + bb.y,
              v2 = acc[r][2] + bb.z, v3 = acc[r][3] + bb.w;
        if (actGelu) { v0 = geluf(v0); v1 = geluf(v1); v2 = geluf(v2); v3 = geluf(v3); }
        float4 out = make_float4(v0, v1, v2, v3);
        *(float4*)&C[(size_t)(row0 + tr * 4 + r) * N + c0 + tc * 4] = out;
    }
}

// ---------------- GAT aggregate: block per node, thread per feature ----------------
// Optional fused residual (layer 3): out = gelu(acc + bias) + (x @ resW + resb)
__global__ void aggregate_kernel(const float* __restrict__ h, const int* __restrict__ nbr,
                                 const float* __restrict__ als, const float* __restrict__ ald,
                                 const float* __restrict__ bias, float* __restrict__ out,
                                 int H, int C,
                                 const float* __restrict__ x6, const float* __restrict__ resW,
                                 const float* __restrict__ resb) {
    int F = H * C;
    int i = blockIdx.x;
    int t = threadIdx.x;
    __shared__ int   s_nbr[17];
    __shared__ float s_e[68];
    __shared__ float s_alpha[68];
    __shared__ float s_m[4], s_inv[4];
    __shared__ float s_x[6];

    if (t < 17) s_nbr[t] = (t < 16) ? nbr[i * KNB + t] : i;
    if (x6 && t >= 24 && t < 30) s_x[t - 24] = x6[i * 6 + (t - 24)];
    __syncthreads();

    int EH = 17 * H;
    if (t < EH) {
        int j = t / H, hh = t - j * H;
        float raw = als[(size_t)s_nbr[j] * H + hh] + ald[(size_t)i * H + hh];
        s_e[t] = raw > 0.f ? raw : 0.2f * raw;
    }
    __syncthreads();
    if (t < H) {
        float m = -1e30f;
        for (int j = 0; j < 17; j++) m = fmaxf(m, s_e[j * H + t]);
        float den = 0.f;
        for (int j = 0; j < 17; j++) den += expf(s_e[j * H + t] - m);
        s_m[t] = m; s_inv[t] = 1.0f / den;
    }
    __syncthreads();
    if (t < EH) {
        int hh = t % H;
        s_alpha[t] = expf(s_e[t] - s_m[hh]) * s_inv[hh];
    }
    __syncthreads();

    int hh = t / C;
    float acc = 0.f;
#pragma unroll 17
    for (int j = 0; j < 17; j++) {
        acc += s_alpha[j * H + hh] * h[(size_t)s_nbr[j] * F + t];
    }
    float v = geluf(acc + bias[t]);
    if (x6) {
        float res = resb[t];
#pragma unroll
        for (int d = 0; d < 6; d++) res += s_x[d] * resW[d * 128 + t];
        v += res;
    }
    out[(size_t)i * F + t] = v;
}

// ---------------- final: out[i, 0..5] = t2[i] @ m3_W + m3_b ----------------
__global__ void final_kernel(const float* __restrict__ A, const float* __restrict__ W,
                             const float* __restrict__ b, float* __restrict__ out) {
    __shared__ float Ws[64 * 6];
    __shared__ float sb[6];
    int t = threadIdx.x;
    for (int k = t; k < 64 * 6; k += blockDim.x) Ws[k] = W[k];
    if (t < 6) sb[t] = b[t];
    __syncthreads();

    int i = blockIdx.x * blockDim.x + t;
    if (i >= NN) return;
    float acc[6];
#pragma unroll
    for (int o = 0; o < 6; o++) acc[o] = sb[o];
    const float4* Ar = (const float4*)(A + (size_t)i * 64);
#pragma unroll
    for (int k4 = 0; k4 < 16; k4++) {
        float4 v = Ar[k4];
        int k = k4 * 4;
#pragma unroll
        for (int o = 0; o < 6; o++) {
            acc[o] += v.x * Ws[(k + 0) * 6 + o];
            acc[o] += v.y * Ws[(k + 1) * 6 + o];
            acc[o] += v.z * Ws[(k + 2) * 6 + o];
            acc[o] += v.w * Ws[(k + 3) * 6 + o];
        }
    }
#pragma unroll
    for (int o = 0; o < 6; o++) out[(size_t)i * 6 + o] = acc[o];
}

// ---------------- launch ----------------
extern "C" void kernel_launch(void* const* d_in, const int* in_sizes, int n_in,
                              void* d_out, int out_size) {
    const float* x    = (const float*)d_in[0];
    const float* W1   = (const float*)d_in[1];
    const float* as1  = (const float*)d_in[2];
    const float* ad1  = (const float*)d_in[3];
    const float* b1   = (const float*)d_in[4];
    const float* W2   = (const float*)d_in[5];
    const float* as2  = (const float*)d_in[6];
    const float* ad2  = (const float*)d_in[7];
    const float* b2   = (const float*)d_in[8];
    const float* W3   = (const float*)d_in[9];
    const float* as3  = (const float*)d_in[10];
    const float* ad3  = (const float*)d_in[11];
    const float* b3   = (const float*)d_in[12];
    const float* resW = (const float*)d_in[13];
    const float* resb = (const float*)d_in[14];
    const float* m1W  = (const float*)d_in[15];
    const float* m1b  = (const float*)d_in[16];
    const float* m2W  = (const float*)d_in[17];
    const float* m2b  = (const float*)d_in[18];
    const float* m3W  = (const float*)d_in[19];
    const float* m3b  = (const float*)d_in[20];

    float *xp, *h, *a0, *a1, *als, *ald;
    int* nbr;
    cudaGetSymbolAddress((void**)&xp,  g_xp);
    cudaGetSymbolAddress((void**)&nbr, g_nbr);
    cudaGetSymbolAddress((void**)&h,   g_h);
    cudaGetSymbolAddress((void**)&a0,  g_act0);
    cudaGetSymbolAddress((void**)&a1,  g_act1);
    cudaGetSymbolAddress((void**)&als, g_als);
    cudaGetSymbolAddress((void**)&ald, g_ald);

    prep_kernel<<<NN / 256, 256>>>(x, xp);
    knn_kernel<<<NN / 8, 256>>>(xp, nbr);

    // GAT layer 1 (6 -> 256, H=4, C=64)
    zero2_kernel<<<(NN * 4 + 255) / 256, 256>>>(als, ald, NN * 4);
    gemm_rt_kernel<<<dim3(NN / 64, 4), 256>>>(x, W1, nullptr, h, 6, 256, 0,
                                              as1, ad1, als, ald, 4, 6);
    aggregate_kernel<<<NN, 256>>>(h, nbr, als, ald, b1, a0, 4, 64,
                                  nullptr, nullptr, nullptr);

    // GAT layer 2 (256 -> 256, H=4, C=64)
    zero2_kernel<<<(NN * 4 + 255) / 256, 256>>>(als, ald, NN * 4);
    gemm_rt_kernel<<<dim3(NN / 64, 4), 256>>>(a0, W2, nullptr, h, 256, 256, 0,
                                              as2, ad2, als, ald, 4, 6);
    aggregate_kernel<<<NN, 256>>>(h, nbr, als, ald, b2, a1, 4, 64,
                                  nullptr, nullptr, nullptr);

    // GAT layer 3 (256 -> 128, H=1, C=128) + fused residual
    zero2_kernel<<<(NN + 255) / 256, 256>>>(als, ald, NN);
    gemm_rt_kernel<<<dim3(NN / 64, 2), 256>>>(a1, W3, nullptr, h, 256, 128, 0,
                                              as3, ad3, als, ald, 1, 7);
    aggregate_kernel<<<NN, 128>>>(h, nbr, als, ald, b3, a0, 1, 128,
                                  x, resW, resb);

    // MLP
    gemm_rt_kernel<<<dim3(NN / 64, 2), 256>>>(a0, m1W, m1b, a1, 128, 128, 1,
                                              nullptr, nullptr, nullptr, nullptr, 0, 0);
    gemm_rt_kernel<<<dim3(NN / 64, 1), 256>>>(a1, m2W, m2b, h, 128, 64, 1,
                                              nullptr, nullptr, nullptr, nullptr, 0, 0);
    final_kernel<<<NN / 128, 128>>>(h, m3W, m3b, (float*)d_out);
}

// round 4
// speedup vs baseline: 1.9832x; 1.0656x over previous
#include <cuda_runtime.h>
#include <math.h>

#define NN 16384      // total nodes (B*N)
#define NB 4096       // nodes per batch
#define KNB 16        // kNN K

// ---------------- scratch (no allocations allowed) ----------------
__device__ float g_xp[NN * 8];
__device__ int   g_nbr[NN * KNB];
__device__ float g_h[NN * 256];
__device__ float g_act0[NN * 256];
__device__ float g_act1[NN * 256];
__device__ float g_als[NN * 4];
__device__ float g_ald[NN * 4];

__device__ __forceinline__ float geluf(float v) {
    return 0.5f * v * (1.0f + erff(v * 0.7071067811865476f));
}

// ---------------- prep: pad + squared norms ----------------
__global__ void prep_kernel(const float* __restrict__ x, float* __restrict__ xp) {
    int i = blockIdx.x * blockDim.x + threadIdx.x;
    if (i >= NN) return;
    float s = 0.f;
    float v[6];
#pragma unroll
    for (int d = 0; d < 6; d++) { v[d] = x[i * 6 + d]; s += v[d] * v[d]; }
#pragma unroll
    for (int d = 0; d < 6; d++) xp[i * 8 + d] = v[d];
    xp[i * 8 + 6] = s;
    xp[i * 8 + 7] = 0.f;
}

// ---------------- zero helper ----------------
__global__ void zero2_kernel(float* __restrict__ a, float* __restrict__ b, int n) {
    int i = blockIdx.x * blockDim.x + threadIdx.x;
    if (i < n) { a[i] = 0.f; b[i] = 0.f; }
}

// ---------------- kNN: warp per query; distributed global top-16 ----------------
__global__ void knn_kernel(const float* __restrict__ xp, int* __restrict__ nbr) {
    int gwarp = (blockIdx.x * blockDim.x + threadIdx.x) >> 5;
    int lane = threadIdx.x & 31;
    if (gwarp >= NN) return;
    int q = gwarp;
    int base = q & ~(NB - 1);

    const float4* xp4 = (const float4*)xp;
    float4 q0 = xp4[(size_t)q * 2];
    float4 q1 = xp4[(size_t)q * 2 + 1];
    float sqq = q1.z;

    float s_d = 1e30f;
    int   s_i = -1;

    for (int j0 = 0; j0 < NB; j0 += 32) {
        int g = base + j0 + lane;
        float4 c0 = xp4[(size_t)g * 2];
        float4 c1 = xp4[(size_t)g * 2 + 1];
        float dot = q0.x * c0.x + q0.y * c0.y + q0.z * c0.z + q0.w * c0.w
                  + q1.x * c1.x + q1.y * c1.y;
        float d2 = sqq + c1.z - 2.0f * dot;
        if (g == q) d2 = 1e30f;

        float thresh = __shfl_sync(0xffffffffu, s_d, 15);
        unsigned ball = __ballot_sync(0xffffffffu, d2 < thresh);
        while (ball) {
            int src = __ffs(ball) - 1;
            ball &= ball - 1;
            float v  = __shfl_sync(0xffffffffu, d2, src);
            int   vi = base + j0 + src;
            float up_d = __shfl_up_sync(0xffffffffu, s_d, 1);
            int   up_i = __shfl_up_sync(0xffffffffu, s_i, 1);
            unsigned lt = __ballot_sync(0xffffffffu, s_d < v);
            int pos = __popc(lt);
            if (pos < 16) {
                if (lane == pos)      { s_d = v;    s_i = vi;   }
                else if (lane > pos)  { s_d = up_d; s_i = up_i; }
            }
        }
    }
    if (lane < 16) nbr[q * KNB + lane] = s_i;
}

// ---------------- layer-1 GEMM (K=6) + direct logits, warp per node ------------
__global__ void gemm6_kernel(const float* __restrict__ x, const float* __restrict__ W,
                             const float* __restrict__ a_s, const float* __restrict__ a_d,
                             float* __restrict__ h, float* __restrict__ als,
                             float* __restrict__ ald) {
    __shared__ float sW[6 * 256];
    __shared__ float sAs[256], sAd[256];
    int t = threadIdx.x;
    for (int i = t; i < 6 * 256; i += 256) sW[i] = W[i];
    sAs[t] = a_s[t]; sAd[t] = a_d[t];
    __syncthreads();

    int warp = t >> 5, lane = t & 31;
    int node = blockIdx.x * 8 + warp;
    float xr[6];
#pragma unroll
    for (int d = 0; d < 6; d++) xr[d] = x[node * 6 + d];
    int cbase = lane * 8;
    float out[8];
#pragma unroll
    for (int c = 0; c < 8; c++) {
        float s = 0.f;
#pragma unroll
        for (int d = 0; d < 6; d++) s += xr[d] * sW[d * 256 + cbase + c];
        out[c] = s;
    }
    *(float4*)&h[(size_t)node * 256 + cbase] = make_float4(out[0], out[1], out[2], out[3]);
    *(float4*)&h[(size_t)node * 256 + cbase + 4] = make_float4(out[4], out[5], out[6], out[7]);

    float ps = 0.f, pd = 0.f;
#pragma unroll
    for (int c = 0; c < 8; c++) {
        ps += out[c] * sAs[cbase + c];
        pd += out[c] * sAd[cbase + c];
    }
#pragma unroll
    for (int off = 1; off <= 4; off <<= 1) {
        ps += __shfl_xor_sync(0xffffffffu, ps, off);
        pd += __shfl_xor_sync(0xffffffffu, pd, off);
    }
    if ((lane & 7) == 0) {
        int hh = lane >> 3;
        als[node * 4 + hh] = ps;
        ald[node * 4 + hh] = pd;
    }
}

// ---------------- main GEMM: 128x64 block tile, 8x4 per thread, prefetch -------
// C[M,N] = A[M,K] @ W[K,N]; K % 16 == 0, K % 4 == 0; N % 64 == 0.
__global__ void gemm_tile_kernel(const float* __restrict__ A, const float* __restrict__ W,
                                 const float* __restrict__ bias, float* __restrict__ C,
                                 int K, int N, int actGelu,
                                 const float* __restrict__ a_s, const float* __restrict__ a_d,
                                 float* __restrict__ als, float* __restrict__ ald,
                                 int H, int headShift) {
    __shared__ float As[16][136];
    __shared__ float Ws[16][64];

    int t = threadIdx.x;
    int tx = t & 15;          // col group (4 cols)
    int ty = t >> 4;          // row group (8 rows)
    int row0 = blockIdx.x * 128;
    int c0 = blockIdx.y * 64;

    float acc[8][4];
#pragma unroll
    for (int r = 0; r < 8; r++)
#pragma unroll
        for (int c = 0; c < 4; c++) acc[r][c] = 0.f;

    float4 aReg[2], wReg;
    int aR[2], aKq[2];
#pragma unroll
    for (int i = 0; i < 2; i++) {
        int lin = t + i * 256;
        aR[i] = lin >> 2;
        aKq[i] = lin & 3;
    }
    int wK = t >> 4, wC = (t & 15) * 4;

    // prefetch chunk 0
#pragma unroll
    for (int i = 0; i < 2; i++)
        aReg[i] = *(const float4*)&A[(size_t)(row0 + aR[i]) * K + aKq[i] * 4];
    wReg = *(const float4*)&W[(size_t)wK * N + c0 + wC];

    int nchunks = K >> 4;
    for (int ch = 0; ch < nchunks; ch++) {
        // store current chunk to smem
#pragma unroll
        for (int i = 0; i < 2; i++) {
            As[aKq[i] * 4 + 0][aR[i]] = aReg[i].x;
            As[aKq[i] * 4 + 1][aR[i]] = aReg[i].y;
            As[aKq[i] * 4 + 2][aR[i]] = aReg[i].z;
            As[aKq[i] * 4 + 3][aR[i]] = aReg[i].w;
        }
        *(float4*)&Ws[wK][wC] = wReg;
        __syncthreads();

        // prefetch next chunk
        if (ch + 1 < nchunks) {
            int k0 = (ch + 1) << 4;
#pragma unroll
            for (int i = 0; i < 2; i++)
                aReg[i] = *(const float4*)&A[(size_t)(row0 + aR[i]) * K + k0 + aKq[i] * 4];
            wReg = *(const float4*)&W[(size_t)(k0 + wK) * N + c0 + wC];
        }

#pragma unroll
        for (int k = 0; k < 16; k++) {
            float4 a0 = *(const float4*)&As[k][ty * 8];
            float4 a1 = *(const float4*)&As[k][ty * 8 + 4];
            float4 wv = *(const float4*)&Ws[k][tx * 4];
            acc[0][0] += a0.x * wv.x; acc[0][1] += a0.x * wv.y; acc[0][2] += a0.x * wv.z; acc[0][3] += a0.x * wv.w;
            acc[1][0] += a0.y * wv.x; acc[1][1] += a0.y * wv.y; acc[1][2] += a0.y * wv.z; acc[1][3] += a0.y * wv.w;
            acc[2][0] += a0.z * wv.x; acc[2][1] += a0.z * wv.y; acc[2][2] += a0.z * wv.z; acc[2][3] += a0.z * wv.w;
            acc[3][0] += a0.w * wv.x; acc[3][1] += a0.w * wv.y; acc[3][2] += a0.w * wv.z; acc[3][3] += a0.w * wv.w;
            acc[4][0] += a1.x * wv.x; acc[4][1] += a1.x * wv.y; acc[4][2] += a1.x * wv.z; acc[4][3] += a1.x * wv.w;
            acc[5][0] += a1.y * wv.x; acc[5][1] += a1.y * wv.y; acc[5][2] += a1.y * wv.z; acc[5][3] += a1.y * wv.w;
            acc[6][0] += a1.z * wv.x; acc[6][1] += a1.z * wv.y; acc[6][2] += a1.z * wv.z; acc[6][3] += a1.z * wv.w;
            acc[7][0] += a1.w * wv.x; acc[7][1] += a1.w * wv.y; acc[7][2] += a1.w * wv.z; acc[7][3] += a1.w * wv.w;
        }
        __syncthreads();
    }

    // fused attention logits (atomic accumulate per head)
    if (als) {
        float4 asv = *(const float4*)&a_s[c0 + tx * 4];
        float4 adv = *(const float4*)&a_d[c0 + tx * 4];
        float ps[8], pd[8];
#pragma unroll
        for (int r = 0; r < 8; r++) {
            ps[r] = acc[r][0] * asv.x + acc[r][1] * asv.y + acc[r][2] * asv.z + acc[r][3] * asv.w;
            pd[r] = acc[r][0] * adv.x + acc[r][1] * adv.y + acc[r][2] * adv.z + acc[r][3] * adv.w;
        }
#pragma unroll
        for (int off = 1; off <= 8; off <<= 1) {
#pragma unroll
            for (int r = 0; r < 8; r++) {
                ps[r] += __shfl_xor_sync(0xffffffffu, ps[r], off);
                pd[r] += __shfl_xor_sync(0xffffffffu, pd[r], off);
            }
        }
        if (tx == 0) {
            int hb = c0 >> headShift;
#pragma unroll
            for (int r = 0; r < 8; r++) {
                atomicAdd(&als[(size_t)(row0 + ty * 8 + r) * H + hb], ps[r]);
                atomicAdd(&ald[(size_t)(row0 + ty * 8 + r) * H + hb], pd[r]);
            }
        }
    }

    float4 bb = make_float4(0.f, 0.f, 0.f, 0.f);
    if (bias) bb = *(const float4*)&bias[c0 + tx * 4];
#pragma unroll
    for (int r = 0; r < 8; r++) {
        float v0 = acc[r][0] + bb.x, v1 = acc[r][1] + bb.y,
              v2 = acc[r][2] + bb.z, v3 = acc[r][3] + bb.w;
        if (actGelu) { v0 = geluf(v0); v1 = geluf(v1); v2 = geluf(v2); v3 = geluf(v3); }
        *(float4*)&C[(size_t)(row0 + ty * 8 + r) * N + c0 + tx * 4] =
            make_float4(v0, v1, v2, v3);
    }
}

// ---------------- GAT aggregate: block per node, thread per feature ----------------
__global__ void aggregate_kernel(const float* __restrict__ h, const int* __restrict__ nbr,
                                 const float* __restrict__ als, const float* __restrict__ ald,
                                 const float* __restrict__ bias, float* __restrict__ out,
                                 int H, int C,
                                 const float* __restrict__ x6, const float* __restrict__ resW,
                                 const float* __restrict__ resb) {
    int F = H * C;
    int i = blockIdx.x;
    int t = threadIdx.x;
    __shared__ int   s_nbr[17];
    __shared__ float s_e[68];
    __shared__ float s_alpha[68];
    __shared__ float s_m[4], s_inv[4];
    __shared__ float s_x[6];

    if (t < 17) s_nbr[t] = (t < 16) ? nbr[i * KNB + t] : i;
    if (x6 && t >= 24 && t < 30) s_x[t - 24] = x6[i * 6 + (t - 24)];
    __syncthreads();

    int EH = 17 * H;
    if (t < EH) {
        int j = t / H, hh = t - j * H;
        float raw = als[(size_t)s_nbr[j] * H + hh] + ald[(size_t)i * H + hh];
        s_e[t] = raw > 0.f ? raw : 0.2f * raw;
    }
    __syncthreads();
    if (t < H) {
        float m = -1e30f;
        for (int j = 0; j < 17; j++) m = fmaxf(m, s_e[j * H + t]);
        float den = 0.f;
        for (int j = 0; j < 17; j++) den += expf(s_e[j * H + t] - m);
        s_m[t] = m; s_inv[t] = 1.0f / den;
    }
    __syncthreads();
    if (t < EH) {
        int hh = t % H;
        s_alpha[t] = expf(s_e[t] - s_m[hh]) * s_inv[hh];
    }
    __syncthreads();

    int hh = t / C;
    float acc = 0.f;
#pragma unroll 17
    for (int j = 0; j < 17; j++) {
        acc += s_alpha[j * H + hh] * h[(size_t)s_nbr[j] * F + t];
    }
    float v = geluf(acc + bias[t]);
    if (x6) {
        float res = resb[t];
#pragma unroll
        for (int d = 0; d < 6; d++) res += s_x[d] * resW[d * 128 + t];
        v += res;
    }
    out[(size_t)i * F + t] = v;
}

// ---------------- final: out[i, 0..5] = t2[i] @ m3_W + m3_b ----------------
__global__ void final_kernel(const float* __restrict__ A, const float* __restrict__ W,
                             const float* __restrict__ b, float* __restrict__ out) {
    __shared__ float Ws[64 * 6];
    __shared__ float sb[6];
    int t = threadIdx.x;
    for (int k = t; k < 64 * 6; k += blockDim.x) Ws[k] = W[k];
    if (t < 6) sb[t] = b[t];
    __syncthreads();

    int i = blockIdx.x * blockDim.x + t;
    if (i >= NN) return;
    float acc[6];
#pragma unroll
    for (int o = 0; o < 6; o++) acc[o] = sb[o];
    const float4* Ar = (const float4*)(A + (size_t)i * 64);
#pragma unroll
    for (int k4 = 0; k4 < 16; k4++) {
        float4 v = Ar[k4];
        int k = k4 * 4;
#pragma unroll
        for (int o = 0; o < 6; o++) {
            acc[o] += v.x * Ws[(k + 0) * 6 + o];
            acc[o] += v.y * Ws[(k + 1) * 6 + o];
            acc[o] += v.z * Ws[(k + 2) * 6 + o];
            acc[o] += v.w * Ws[(k + 3) * 6 + o];
        }
    }
#pragma unroll
    for (int o = 0; o < 6; o++) out[(size_t)i * 6 + o] = acc[o];
}

// ---------------- launch ----------------
extern "C" void kernel_launch(void* const* d_in, const int* in_sizes, int n_in,
                              void* d_out, int out_size) {
    const float* x    = (const float*)d_in[0];
    const float* W1   = (const float*)d_in[1];
    const float* as1  = (const float*)d_in[2];
    const float* ad1  = (const float*)d_in[3];
    const float* b1   = (const float*)d_in[4];
    const float* W2   = (const float*)d_in[5];
    const float* as2  = (const float*)d_in[6];
    const float* ad2  = (const float*)d_in[7];
    const float* b2   = (const float*)d_in[8];
    const float* W3   = (const float*)d_in[9];
    const float* as3  = (const float*)d_in[10];
    const float* ad3  = (const float*)d_in[11];
    const float* b3   = (const float*)d_in[12];
    const float* resW = (const float*)d_in[13];
    const float* resb = (const float*)d_in[14];
    const float* m1W  = (const float*)d_in[15];
    const float* m1b  = (const float*)d_in[16];
    const float* m2W  = (const float*)d_in[17];
    const float* m2b  = (const float*)d_in[18];
    const float* m3W  = (const float*)d_in[19];
    const float* m3b  = (const float*)d_in[20];

    float *xp, *h, *a0, *a1, *als, *ald;
    int* nbr;
    cudaGetSymbolAddress((void**)&xp,  g_xp);
    cudaGetSymbolAddress((void**)&nbr, g_nbr);
    cudaGetSymbolAddress((void**)&h,   g_h);
    cudaGetSymbolAddress((void**)&a0,  g_act0);
    cudaGetSymbolAddress((void**)&a1,  g_act1);
    cudaGetSymbolAddress((void**)&als, g_als);
    cudaGetSymbolAddress((void**)&ald, g_ald);

    prep_kernel<<<NN / 256, 256>>>(x, xp);
    knn_kernel<<<NN / 8, 256>>>(xp, nbr);

    // GAT layer 1 (6 -> 256, H=4, C=64): fused GEMM + direct logits (no atomics)
    gemm6_kernel<<<NN / 8, 256>>>(x, W1, as1, ad1, h, als, ald);
    aggregate_kernel<<<NN, 256>>>(h, nbr, als, ald, b1, a0, 4, 64,
                                  nullptr, nullptr, nullptr);

    // GAT layer 2 (256 -> 256, H=4, C=64)
    zero2_kernel<<<(NN * 4 + 255) / 256, 256>>>(als, ald, NN * 4);
    gemm_tile_kernel<<<dim3(NN / 128, 4), 256>>>(a0, W2, nullptr, h, 256, 256, 0,
                                                 as2, ad2, als, ald, 4, 6);
    aggregate_kernel<<<NN, 256>>>(h, nbr, als, ald, b2, a1, 4, 64,
                                  nullptr, nullptr, nullptr);

    // GAT layer 3 (256 -> 128, H=1, C=128) + fused residual
    zero2_kernel<<<(NN + 255) / 256, 256>>>(als, ald, NN);
    gemm_tile_kernel<<<dim3(NN / 128, 2), 256>>>(a1, W3, nullptr, h, 256, 128, 0,
                                                 as3, ad3, als, ald, 1, 7);
    aggregate_kernel<<<NN, 128>>>(h, nbr, als, ald, b3, a0, 1, 128,
                                  x, resW, resb);

    // MLP
    gemm_tile_kernel<<<dim3(NN / 128, 2), 256>>>(a0, m1W, m1b, a1, 128, 128, 1,
                                                 nullptr, nullptr, nullptr, nullptr, 0, 0);
    gemm_tile_kernel<<<dim3(NN / 128, 1), 256>>>(a1, m2W, m2b, h, 128, 64, 1,
                                                 nullptr, nullptr, nullptr, nullptr, 0, 0);
    final_kernel<<<NN / 128, 128>>>(h, m3W, m3b, (float*)d_out);
}

// round 5
// speedup vs baseline: 2.3335x; 1.1766x over previous
#include <cuda_runtime.h>
#include <math.h>

#define NN 16384      // total nodes (B*N)
#define NB 4096       // nodes per batch
#define KNB 16        // kNN K

// ---------------- scratch ----------------
__device__ float g_xp[NN * 8];
__device__ int   g_nbr[NN * KNB];
__device__ float g_h[NN * 256];
__device__ float g_act0[NN * 256];
__device__ float g_act1[NN * 256];
__device__ float g_als[NN * 4];
__device__ float g_ald[NN * 4];

__device__ __forceinline__ float geluf(float v) {
    return 0.5f * v * (1.0f + erff(v * 0.7071067811865476f));
}

// ---------------- prep ----------------
__global__ void prep_kernel(const float* __restrict__ x, float* __restrict__ xp) {
    int i = blockIdx.x * blockDim.x + threadIdx.x;
    if (i >= NN) return;
    float s = 0.f;
    float v[6];
#pragma unroll
    for (int d = 0; d < 6; d++) { v[d] = x[i * 6 + d]; s += v[d] * v[d]; }
#pragma unroll
    for (int d = 0; d < 6; d++) xp[i * 8 + d] = v[d];
    xp[i * 8 + 6] = s;
    xp[i * 8 + 7] = 0.f;
}

// ---------------- zero helper ----------------
__global__ void zero2_kernel(float* __restrict__ a, float* __restrict__ b, int n) {
    int i = blockIdx.x * blockDim.x + threadIdx.x;
    if (i < n) { a[i] = 0.f; b[i] = 0.f; }
}

// ---------------- kNN ----------------
__global__ void knn_kernel(const float* __restrict__ xp, int* __restrict__ nbr) {
    int gwarp = (blockIdx.x * blockDim.x + threadIdx.x) >> 5;
    int lane = threadIdx.x & 31;
    if (gwarp >= NN) return;
    int q = gwarp;
    int base = q & ~(NB - 1);

    const float4* xp4 = (const float4*)xp;
    float4 q0 = xp4[(size_t)q * 2];
    float4 q1 = xp4[(size_t)q * 2 + 1];
    float sqq = q1.z;

    float s_d = 1e30f;
    int   s_i = -1;

    for (int j0 = 0; j0 < NB; j0 += 32) {
        int g = base + j0 + lane;
        float4 c0 = xp4[(size_t)g * 2];
        float4 c1 = xp4[(size_t)g * 2 + 1];
        float dot = q0.x * c0.x + q0.y * c0.y + q0.z * c0.z + q0.w * c0.w
                  + q1.x * c1.x + q1.y * c1.y;
        float d2 = sqq + c1.z - 2.0f * dot;
        if (g == q) d2 = 1e30f;

        float thresh = __shfl_sync(0xffffffffu, s_d, 15);
        unsigned ball = __ballot_sync(0xffffffffu, d2 < thresh);
        while (ball) {
            int src = __ffs(ball) - 1;
            ball &= ball - 1;
            float v  = __shfl_sync(0xffffffffu, d2, src);
            int   vi = base + j0 + src;
            float up_d = __shfl_up_sync(0xffffffffu, s_d, 1);
            int   up_i = __shfl_up_sync(0xffffffffu, s_i, 1);
            unsigned lt = __ballot_sync(0xffffffffu, s_d < v);
            int pos = __popc(lt);
            if (pos < 16) {
                if (lane == pos)      { s_d = v;    s_i = vi;   }
                else if (lane > pos)  { s_d = up_d; s_i = up_i; }
            }
        }
    }
    if (lane < 16) nbr[q * KNB + lane] = s_i;
}

// ---------------- layer-1 GEMM (K=6) + direct logits ----------------
__global__ void gemm6_kernel(const float* __restrict__ x, const float* __restrict__ W,
                             const float* __restrict__ a_s, const float* __restrict__ a_d,
                             float* __restrict__ h, float* __restrict__ als,
                             float* __restrict__ ald) {
    __shared__ float sW[6 * 256];
    __shared__ float sAs[256], sAd[256];
    int t = threadIdx.x;
    for (int i = t; i < 6 * 256; i += 256) sW[i] = W[i];
    sAs[t] = a_s[t]; sAd[t] = a_d[t];
    __syncthreads();

    int warp = t >> 5, lane = t & 31;
    int node = blockIdx.x * 8 + warp;
    float xr[6];
#pragma unroll
    for (int d = 0; d < 6; d++) xr[d] = x[node * 6 + d];
    int cbase = lane * 8;
    float out[8];
#pragma unroll
    for (int c = 0; c < 8; c++) {
        float s = 0.f;
#pragma unroll
        for (int d = 0; d < 6; d++) s += xr[d] * sW[d * 256 + cbase + c];
        out[c] = s;
    }
    *(float4*)&h[(size_t)node * 256 + cbase] = make_float4(out[0], out[1], out[2], out[3]);
    *(float4*)&h[(size_t)node * 256 + cbase + 4] = make_float4(out[4], out[5], out[6], out[7]);

    float ps = 0.f, pd = 0.f;
#pragma unroll
    for (int c = 0; c < 8; c++) {
        ps += out[c] * sAs[cbase + c];
        pd += out[c] * sAd[cbase + c];
    }
#pragma unroll
    for (int off = 1; off <= 4; off <<= 1) {
        ps += __shfl_xor_sync(0xffffffffu, ps, off);
        pd += __shfl_xor_sync(0xffffffffu, pd, off);
    }
    if ((lane & 7) == 0) {
        int hh = lane >> 3;
        als[node * 4 + hh] = ps;
        ald[node * 4 + hh] = pd;
    }
}

// ---------------- main GEMM: 128x64 tile, 8x4 per thread, prefetch ----------------
__global__ void gemm_tile_kernel(const float* __restrict__ A, const float* __restrict__ W,
                                 const float* __restrict__ bias, float* __restrict__ C,
                                 int K, int N, int actGelu,
                                 const float* __restrict__ a_s, const float* __restrict__ a_d,
                                 float* __restrict__ als, float* __restrict__ ald,
                                 int H, int headShift) {
    __shared__ float As[16][136];
    __shared__ float Ws[16][64];

    int t = threadIdx.x;
    int tx = t & 15;
    int ty = t >> 4;
    int row0 = blockIdx.x * 128;
    int c0 = blockIdx.y * 64;

    float acc[8][4];
#pragma unroll
    for (int r = 0; r < 8; r++)
#pragma unroll
        for (int c = 0; c < 4; c++) acc[r][c] = 0.f;

    float4 aReg[2], wReg;
    int aR[2], aKq[2];
#pragma unroll
    for (int i = 0; i < 2; i++) {
        int lin = t + i * 256;
        aR[i] = lin >> 2;
        aKq[i] = lin & 3;
    }
    int wK = t >> 4, wC = (t & 15) * 4;

#pragma unroll
    for (int i = 0; i < 2; i++)
        aReg[i] = *(const float4*)&A[(size_t)(row0 + aR[i]) * K + aKq[i] * 4];
    wReg = *(const float4*)&W[(size_t)wK * N + c0 + wC];

    int nchunks = K >> 4;
    for (int ch = 0; ch < nchunks; ch++) {
#pragma unroll
        for (int i = 0; i < 2; i++) {
            As[aKq[i] * 4 + 0][aR[i]] = aReg[i].x;
            As[aKq[i] * 4 + 1][aR[i]] = aReg[i].y;
            As[aKq[i] * 4 + 2][aR[i]] = aReg[i].z;
            As[aKq[i] * 4 + 3][aR[i]] = aReg[i].w;
        }
        *(float4*)&Ws[wK][wC] = wReg;
        __syncthreads();

        if (ch + 1 < nchunks) {
            int k0 = (ch + 1) << 4;
#pragma unroll
            for (int i = 0; i < 2; i++)
                aReg[i] = *(const float4*)&A[(size_t)(row0 + aR[i]) * K + k0 + aKq[i] * 4];
            wReg = *(const float4*)&W[(size_t)(k0 + wK) * N + c0 + wC];
        }

#pragma unroll
        for (int k = 0; k < 16; k++) {
            float4 a0 = *(const float4*)&As[k][ty * 8];
            float4 a1 = *(const float4*)&As[k][ty * 8 + 4];
            float4 wv = *(const float4*)&Ws[k][tx * 4];
            acc[0][0] += a0.x * wv.x; acc[0][1] += a0.x * wv.y; acc[0][2] += a0.x * wv.z; acc[0][3] += a0.x * wv.w;
            acc[1][0] += a0.y * wv.x; acc[1][1] += a0.y * wv.y; acc[1][2] += a0.y * wv.z; acc[1][3] += a0.y * wv.w;
            acc[2][0] += a0.z * wv.x; acc[2][1] += a0.z * wv.y; acc[2][2] += a0.z * wv.z; acc[2][3] += a0.z * wv.w;
            acc[3][0] += a0.w * wv.x; acc[3][1] += a0.w * wv.y; acc[3][2] += a0.w * wv.z; acc[3][3] += a0.w * wv.w;
            acc[4][0] += a1.x * wv.x; acc[4][1] += a1.x * wv.y; acc[4][2] += a1.x * wv.z; acc[4][3] += a1.x * wv.w;
            acc[5][0] += a1.y * wv.x; acc[5][1] += a1.y * wv.y; acc[5][2] += a1.y * wv.z; acc[5][3] += a1.y * wv.w;
            acc[6][0] += a1.z * wv.x; acc[6][1] += a1.z * wv.y; acc[6][2] += a1.z * wv.z; acc[6][3] += a1.z * wv.w;
            acc[7][0] += a1.w * wv.x; acc[7][1] += a1.w * wv.y; acc[7][2] += a1.w * wv.z; acc[7][3] += a1.w * wv.w;
        }
        __syncthreads();
    }

    if (als) {
        float4 asv = *(const float4*)&a_s[c0 + tx * 4];
        float4 adv = *(const float4*)&a_d[c0 + tx * 4];
        float ps[8], pd[8];
#pragma unroll
        for (int r = 0; r < 8; r++) {
            ps[r] = acc[r][0] * asv.x + acc[r][1] * asv.y + acc[r][2] * asv.z + acc[r][3] * asv.w;
            pd[r] = acc[r][0] * adv.x + acc[r][1] * adv.y + acc[r][2] * adv.z + acc[r][3] * adv.w;
        }
#pragma unroll
        for (int off = 1; off <= 8; off <<= 1) {
#pragma unroll
            for (int r = 0; r < 8; r++) {
                ps[r] += __shfl_xor_sync(0xffffffffu, ps[r], off);
                pd[r] += __shfl_xor_sync(0xffffffffu, pd[r], off);
            }
        }
        if (tx == 0) {
            int hb = c0 >> headShift;
#pragma unroll
            for (int r = 0; r < 8; r++) {
                atomicAdd(&als[(size_t)(row0 + ty * 8 + r) * H + hb], ps[r]);
                atomicAdd(&ald[(size_t)(row0 + ty * 8 + r) * H + hb], pd[r]);
            }
        }
    }

    float4 bb = make_float4(0.f, 0.f, 0.f, 0.f);
    if (bias) bb = *(const float4*)&bias[c0 + tx * 4];
#pragma unroll
    for (int r = 0; r < 8; r++) {
        float v0 = acc[r][0] + bb.x, v1 = acc[r][1] + bb.y,
              v2 = acc[r][2] + bb.z, v3 = acc[r][3] + bb.w;
        if (actGelu) { v0 = geluf(v0); v1 = geluf(v1); v2 = geluf(v2); v3 = geluf(v3); }
        *(float4*)&C[(size_t)(row0 + ty * 8 + r) * N + c0 + tx * 4] =
            make_float4(v0, v1, v2, v3);
    }
}

// ---------------- warp-per-node GAT aggregate (H=4, F=256) ----------------
__global__ void warp_agg4_kernel(const float* __restrict__ h, const int* __restrict__ nbr,
                                 const float* __restrict__ als, const float* __restrict__ ald,
                                 const float* __restrict__ bias, float* __restrict__ out) {
    __shared__ float s_alpha[8][68];   // [warp][head*17 + j]
    int warp = threadIdx.x >> 5, lane = threadIdx.x & 31;
    int i = blockIdx.x * 8 + warp;

    int nbr_j = i;                              // lane 16 = self loop; lanes>16 dummy
    if (lane < 16) nbr_j = nbr[i * KNB + lane];

    // e[j][h] for this lane's j
    float4 sv = *(const float4*)&als[nbr_j * 4];
    float4 dv = *(const float4*)&ald[i * 4];
    float e0 = sv.x + dv.x, e1 = sv.y + dv.y, e2 = sv.z + dv.z, e3 = sv.w + dv.w;
    e0 = e0 > 0.f ? e0 : 0.2f * e0;
    e1 = e1 > 0.f ? e1 : 0.2f * e1;
    e2 = e2 > 0.f ? e2 : 0.2f * e2;
    e3 = e3 > 0.f ? e3 : 0.2f * e3;
    float m0 = lane < 17 ? e0 : -1e30f, m1 = lane < 17 ? e1 : -1e30f;
    float m2 = lane < 17 ? e2 : -1e30f, m3 = lane < 17 ? e3 : -1e30f;
#pragma unroll
    for (int off = 16; off > 0; off >>= 1) {
        m0 = fmaxf(m0, __shfl_xor_sync(0xffffffffu, m0, off));
        m1 = fmaxf(m1, __shfl_xor_sync(0xffffffffu, m1, off));
        m2 = fmaxf(m2, __shfl_xor_sync(0xffffffffu, m2, off));
        m3 = fmaxf(m3, __shfl_xor_sync(0xffffffffu, m3, off));
    }
    float x0 = lane < 17 ? __expf(e0 - m0) : 0.f;
    float x1 = lane < 17 ? __expf(e1 - m1) : 0.f;
    float x2 = lane < 17 ? __expf(e2 - m2) : 0.f;
    float x3 = lane < 17 ? __expf(e3 - m3) : 0.f;
    float d0 = x0, d1 = x1, d2 = x2, d3 = x3;
#pragma unroll
    for (int off = 16; off > 0; off >>= 1) {
        d0 += __shfl_xor_sync(0xffffffffu, d0, off);
        d1 += __shfl_xor_sync(0xffffffffu, d1, off);
        d2 += __shfl_xor_sync(0xffffffffu, d2, off);
        d3 += __shfl_xor_sync(0xffffffffu, d3, off);
    }
    if (lane < 17) {
        s_alpha[warp][0 * 17 + lane] = x0 / d0;
        s_alpha[warp][1 * 17 + lane] = x1 / d1;
        s_alpha[warp][2 * 17 + lane] = x2 / d2;
        s_alpha[warp][3 * 17 + lane] = x3 / d3;
    }
    __syncwarp();

    int fbase = lane * 8;              // this lane's 8 features
    int hh = lane >> 3;                // head = fbase/64
    float4 acc0 = make_float4(0.f, 0.f, 0.f, 0.f);
    float4 acc1 = make_float4(0.f, 0.f, 0.f, 0.f);
#pragma unroll
    for (int j = 0; j < 17; j++) {
        int g = __shfl_sync(0xffffffffu, nbr_j, j);
        float a = s_alpha[warp][hh * 17 + j];
        const float4* p = (const float4*)(h + g * 256 + fbase);
        float4 v0 = p[0], v1 = p[1];
        acc0.x += a * v0.x; acc0.y += a * v0.y; acc0.z += a * v0.z; acc0.w += a * v0.w;
        acc1.x += a * v1.x; acc1.y += a * v1.y; acc1.z += a * v1.z; acc1.w += a * v1.w;
    }
    float4 b0 = *(const float4*)&bias[fbase];
    float4 b1 = *(const float4*)&bias[fbase + 4];
    float4 o0 = make_float4(geluf(acc0.x + b0.x), geluf(acc0.y + b0.y),
                            geluf(acc0.z + b0.z), geluf(acc0.w + b0.w));
    float4 o1 = make_float4(geluf(acc1.x + b1.x), geluf(acc1.y + b1.y),
                            geluf(acc1.z + b1.z), geluf(acc1.w + b1.w));
    *(float4*)&out[i * 256 + fbase] = o0;
    *(float4*)&out[i * 256 + fbase + 4] = o1;
}

// ---------------- warp-per-node GAT aggregate (H=1, F=128) + residual ----------------
__global__ void warp_agg1_kernel(const float* __restrict__ h, const int* __restrict__ nbr,
                                 const float* __restrict__ als, const float* __restrict__ ald,
                                 const float* __restrict__ bias, float* __restrict__ out,
                                 const float* __restrict__ x6, const float* __restrict__ resW,
                                 const float* __restrict__ resb) {
    int warp = threadIdx.x >> 5, lane = threadIdx.x & 31;
    int i = blockIdx.x * 8 + warp;

    int nbr_j = i;
    if (lane < 16) nbr_j = nbr[i * KNB + lane];

    float e = als[nbr_j] + ald[i];
    e = e > 0.f ? e : 0.2f * e;
    float m = lane < 17 ? e : -1e30f;
#pragma unroll
    for (int off = 16; off > 0; off >>= 1)
        m = fmaxf(m, __shfl_xor_sync(0xffffffffu, m, off));
    float xe = lane < 17 ? __expf(e - m) : 0.f;
    float den = xe;
#pragma unroll
    for (int off = 16; off > 0; off >>= 1)
        den += __shfl_xor_sync(0xffffffffu, den, off);
    float alpha = xe / den;

    int fbase = lane * 4;
    float4 acc = make_float4(0.f, 0.f, 0.f, 0.f);
#pragma unroll
    for (int j = 0; j < 17; j++) {
        int g = __shfl_sync(0xffffffffu, nbr_j, j);
        float a = __shfl_sync(0xffffffffu, alpha, j);
        float4 v = *(const float4*)(h + g * 128 + fbase);
        acc.x += a * v.x; acc.y += a * v.y; acc.z += a * v.z; acc.w += a * v.w;
    }
    float4 bb = *(const float4*)&bias[fbase];
    float4 o = make_float4(geluf(acc.x + bb.x), geluf(acc.y + bb.y),
                           geluf(acc.z + bb.z), geluf(acc.w + bb.w));
    // residual: x[i]@resW + resb  (columns fbase..fbase+3)
    float4 r = *(const float4*)&resb[fbase];
#pragma unroll
    for (int d = 0; d < 6; d++) {
        float xv = x6[i * 6 + d];
        float4 w = *(const float4*)&resW[d * 128 + fbase];
        r.x += xv * w.x; r.y += xv * w.y; r.z += xv * w.z; r.w += xv * w.w;
    }
    o.x += r.x; o.y += r.y; o.z += r.z; o.w += r.w;
    *(float4*)&out[i * 128 + fbase] = o;
}

// ---------------- final ----------------
__global__ void final_kernel(const float* __restrict__ A, const float* __restrict__ W,
                             const float* __restrict__ b, float* __restrict__ out) {
    __shared__ float Ws[64 * 6];
    __shared__ float sb[6];
    int t = threadIdx.x;
    for (int k = t; k < 64 * 6; k += blockDim.x) Ws[k] = W[k];
    if (t < 6) sb[t] = b[t];
    __syncthreads();

    int i = blockIdx.x * blockDim.x + t;
    if (i >= NN) return;
    float acc[6];
#pragma unroll
    for (int o = 0; o < 6; o++) acc[o] = sb[o];
    const float4* Ar = (const float4*)(A + (size_t)i * 64);
#pragma unroll
    for (int k4 = 0; k4 < 16; k4++) {
        float4 v = Ar[k4];
        int k = k4 * 4;
#pragma unroll
        for (int o = 0; o < 6; o++) {
            acc[o] += v.x * Ws[(k + 0) * 6 + o];
            acc[o] += v.y * Ws[(k + 1) * 6 + o];
            acc[o] += v.z * Ws[(k + 2) * 6 + o];
            acc[o] += v.w * Ws[(k + 3) * 6 + o];
        }
    }
#pragma unroll
    for (int o = 0; o < 6; o++) out[(size_t)i * 6 + o] = acc[o];
}

// ---------------- launch ----------------
extern "C" void kernel_launch(void* const* d_in, const int* in_sizes, int n_in,
                              void* d_out, int out_size) {
    const float* x    = (const float*)d_in[0];
    const float* W1   = (const float*)d_in[1];
    const float* as1  = (const float*)d_in[2];
    const float* ad1  = (const float*)d_in[3];
    const float* b1   = (const float*)d_in[4];
    const float* W2   = (const float*)d_in[5];
    const float* as2  = (const float*)d_in[6];
    const float* ad2  = (const float*)d_in[7];
    const float* b2   = (const float*)d_in[8];
    const float* W3   = (const float*)d_in[9];
    const float* as3  = (const float*)d_in[10];
    const float* ad3  = (const float*)d_in[11];
    const float* b3   = (const float*)d_in[12];
    const float* resW = (const float*)d_in[13];
    const float* resb = (const float*)d_in[14];
    const float* m1W  = (const float*)d_in[15];
    const float* m1b  = (const float*)d_in[16];
    const float* m2W  = (const float*)d_in[17];
    const float* m2b  = (const float*)d_in[18];
    const float* m3W  = (const float*)d_in[19];
    const float* m3b  = (const float*)d_in[20];

    float *xp, *h, *a0, *a1, *als, *ald;
    int* nbr;
    cudaGetSymbolAddress((void**)&xp,  g_xp);
    cudaGetSymbolAddress((void**)&nbr, g_nbr);
    cudaGetSymbolAddress((void**)&h,   g_h);
    cudaGetSymbolAddress((void**)&a0,  g_act0);
    cudaGetSymbolAddress((void**)&a1,  g_act1);
    cudaGetSymbolAddress((void**)&als, g_als);
    cudaGetSymbolAddress((void**)&ald, g_ald);

    prep_kernel<<<NN / 256, 256>>>(x, xp);
    knn_kernel<<<NN / 8, 256>>>(xp, nbr);

    // GAT layer 1 (6 -> 256, H=4)
    gemm6_kernel<<<NN / 8, 256>>>(x, W1, as1, ad1, h, als, ald);
    warp_agg4_kernel<<<NN / 8, 256>>>(h, nbr, als, ald, b1, a0);

    // GAT layer 2 (256 -> 256, H=4)
    zero2_kernel<<<(NN * 4 + 255) / 256, 256>>>(als, ald, NN * 4);
    gemm_tile_kernel<<<dim3(NN / 128, 4), 256>>>(a0, W2, nullptr, h, 256, 256, 0,
                                                 as2, ad2, als, ald, 4, 6);
    warp_agg4_kernel<<<NN / 8, 256>>>(h, nbr, als, ald, b2, a1);

    // GAT layer 3 (256 -> 128, H=1) + fused residual
    zero2_kernel<<<(NN + 255) / 256, 256>>>(als, ald, NN);
    gemm_tile_kernel<<<dim3(NN / 128, 2), 256>>>(a1, W3, nullptr, h, 256, 128, 0,
                                                 as3, ad3, als, ald, 1, 7);
    warp_agg1_kernel<<<NN / 8, 256>>>(h, nbr, als, ald, b3, a0, x, resW, resb);

    // MLP
    gemm_tile_kernel<<<dim3(NN / 128, 2), 256>>>(a0, m1W, m1b, a1, 128, 128, 1,
                                                 nullptr, nullptr, nullptr, nullptr, 0, 0);
    gemm_tile_kernel<<<dim3(NN / 128, 1), 256>>>(a1, m2W, m2b, h, 128, 64, 1,
                                                 nullptr, nullptr, nullptr, nullptr, 0, 0);
    final_kernel<<<NN / 128, 128>>>(h, m3W, m3b, (float*)d_out);
}